// round 3
// baseline (speedup 1.0000x reference)
#include <cuda.h>
#include <cuda_runtime.h>
#include <cuda_bf16.h>
#include <cstdint>

// ============================================================================
// y[8192,4096] = mean(|W|) * (x[8192,4096] @ sign(W)[4096,4096]^T)
// Base-sm_103 path (no tcgen05): binarize W -> bf16 {±1,0}; split x into
// bf16 hi+lo; mma.sync.m16n8k16 bf16 GEMM with fp32 register accumulators;
// scale in epilogue.
// ============================================================================

#define M_TOTAL 8192
#define N_TOTAL 4096
#define K_TOTAL 4096

#define CTA_M 128
#define CTA_N 128
#define K_STEP 32
#define NK (K_TOTAL / K_STEP)    // 128
#define STAGES 4

// SMEM layout per stage: Ahi[128][32] bf16 rows padded to 80B, Alo same, B same
#define ROW_BYTES 80                       // 64 data + 16 pad (conflict-free)
#define TILE_BYTES (128 * ROW_BYTES)       // 10240
#define OFF_AHI 0
#define OFF_ALO TILE_BYTES
#define OFF_B   (2 * TILE_BYTES)
#define STAGE_BYTES (3 * TILE_BYTES)       // 30720
#define SMEM_TOTAL (STAGES * STAGE_BYTES)  // 122880

// ---------------------------------------------------------------------------
// Device scratch (allocation-free rule: __device__ globals)
// ---------------------------------------------------------------------------
__device__ __align__(1024) __nv_bfloat16 g_Ahi[(size_t)M_TOTAL * K_TOTAL];
__device__ __align__(1024) __nv_bfloat16 g_Alo[(size_t)M_TOTAL * K_TOTAL];
__device__ __align__(1024) __nv_bfloat16 g_Bsign[(size_t)N_TOTAL * K_TOTAL];
__device__ float g_partials[1024];
__device__ float g_scale;

// ---------------------------------------------------------------------------
// PTX helpers (sm_80-era, legal on base sm_103)
// ---------------------------------------------------------------------------
__device__ __forceinline__ uint32_t smem_to_u32(const void* p) {
    uint32_t a;
    asm("{ .reg .u64 t; cvta.to.shared.u64 t, %1; cvt.u32.u64 %0, t; }" : "=r"(a) : "l"(p));
    return a;
}

__device__ __forceinline__ void cp_async16(uint32_t dst, const void* src) {
    asm volatile("cp.async.cg.shared.global [%0], [%1], 16;" :: "r"(dst), "l"(src) : "memory");
}
__device__ __forceinline__ void cp_commit() {
    asm volatile("cp.async.commit_group;" ::: "memory");
}
template <int N>
__device__ __forceinline__ void cp_wait() {
    asm volatile("cp.async.wait_group %0;" :: "n"(N) : "memory");
}

__device__ __forceinline__ uint32_t lds32(uint32_t addr) {
    uint32_t v;
    asm volatile("ld.shared.b32 %0, [%1];" : "=r"(v) : "r"(addr));
    return v;
}

__device__ __forceinline__ void mma16816(float& d0, float& d1, float& d2, float& d3,
                                         uint32_t a0, uint32_t a1, uint32_t a2, uint32_t a3,
                                         uint32_t b0, uint32_t b1) {
    asm volatile(
        "mma.sync.aligned.m16n8k16.row.col.f32.bf16.bf16.f32 "
        "{%0,%1,%2,%3}, {%4,%5,%6,%7}, {%8,%9}, {%0,%1,%2,%3};"
        : "+f"(d0), "+f"(d1), "+f"(d2), "+f"(d3)
        : "r"(a0), "r"(a1), "r"(a2), "r"(a3), "r"(b0), "r"(b1));
}

// ---------------------------------------------------------------------------
// Prep kernel 1: binarize W -> bf16 sign AND partial |W| sums (deterministic)
// ---------------------------------------------------------------------------
__global__ void binarize_reduce_kernel(const float* __restrict__ W) {
    __shared__ float sdata[256];
    size_t base = (size_t)blockIdx.x * 16384;
    float s = 0.0f;
    for (int i = threadIdx.x; i < 16384; i += 256) {
        float w = W[base + i];
        s += fabsf(w);
        float sg = (w > 0.0f) ? 1.0f : ((w < 0.0f) ? -1.0f : 0.0f);
        g_Bsign[base + i] = __float2bfloat16(sg);
    }
    sdata[threadIdx.x] = s;
    __syncthreads();
    for (int off = 128; off > 0; off >>= 1) {
        if (threadIdx.x < off) sdata[threadIdx.x] += sdata[threadIdx.x + off];
        __syncthreads();
    }
    if (threadIdx.x == 0) g_partials[blockIdx.x] = sdata[0];
}

__global__ void finalize_scale_kernel() {
    __shared__ float sdata[256];
    int t = threadIdx.x;
    float s = 0.0f;
    #pragma unroll
    for (int i = 0; i < 4; i++) s += g_partials[t * 4 + i];
    sdata[t] = s;
    __syncthreads();
    for (int off = 128; off > 0; off >>= 1) {
        if (t < off) sdata[t] += sdata[t + off];
        __syncthreads();
    }
    if (t == 0) g_scale = sdata[0] * (1.0f / 16777216.0f);
}

// Prep kernel 3: x (fp32) -> hi/lo bf16 split. 8388608 float4 vectors.
__global__ void convert_x_kernel(const float* __restrict__ x) {
    size_t i = (size_t)blockIdx.x * 256 + threadIdx.x;
    float4 v = reinterpret_cast<const float4*>(x)[i];
    __nv_bfloat16 h0 = __float2bfloat16(v.x);
    __nv_bfloat16 h1 = __float2bfloat16(v.y);
    __nv_bfloat16 h2 = __float2bfloat16(v.z);
    __nv_bfloat16 h3 = __float2bfloat16(v.w);
    __nv_bfloat16 l0 = __float2bfloat16(v.x - __bfloat162float(h0));
    __nv_bfloat16 l1 = __float2bfloat16(v.y - __bfloat162float(h1));
    __nv_bfloat16 l2 = __float2bfloat16(v.z - __bfloat162float(h2));
    __nv_bfloat16 l3 = __float2bfloat16(v.w - __bfloat162float(h3));
    ushort4 hv = make_ushort4(__bfloat16_as_ushort(h0), __bfloat16_as_ushort(h1),
                              __bfloat16_as_ushort(h2), __bfloat16_as_ushort(h3));
    ushort4 lv = make_ushort4(__bfloat16_as_ushort(l0), __bfloat16_as_ushort(l1),
                              __bfloat16_as_ushort(l2), __bfloat16_as_ushort(l3));
    reinterpret_cast<ushort4*>(g_Ahi)[i] = hv;
    reinterpret_cast<ushort4*>(g_Alo)[i] = lv;
}

// ---------------------------------------------------------------------------
// GEMM kernel: sm80-style multistage cp.async + mma.sync
// 256 threads = 8 warps, warp grid 2(M) x 4(N), warp tile 64x32
// ---------------------------------------------------------------------------
__global__ void __launch_bounds__(256, 1) gemm_kernel(float* __restrict__ out) {
    extern __shared__ __align__(128) char smem[];
    const uint32_t smem_base = smem_to_u32(smem);

    const int tid = threadIdx.x;
    const int lane = tid & 31;
    const int wid = tid >> 5;
    const int wm = wid & 1;       // 0..1
    const int wn = wid >> 1;      // 0..3
    const int ntile = blockIdx.x; // 0..31
    const int mtile = blockIdx.y; // 0..63

    // ---- cp.async source pointers for this thread ----
    // Each stage: 3 tiles x 512 16B-chunks; thread handles chunks tid, tid+256 per tile.
    const int c0 = tid;            // chunk id rep 0
    const int c1 = tid + 256;      // chunk id rep 1
    const int r0c = c0 >> 2, q0 = c0 & 3;
    const int r1c = c1 >> 2, q1 = c1 & 3;

    const char* pAhi = (const char*)g_Ahi + (size_t)(mtile * 128 + r0c) * 8192 + q0 * 16;
    const char* pAhi2 = (const char*)g_Ahi + (size_t)(mtile * 128 + r1c) * 8192 + q1 * 16;
    const char* pAlo = (const char*)g_Alo + (size_t)(mtile * 128 + r0c) * 8192 + q0 * 16;
    const char* pAlo2 = (const char*)g_Alo + (size_t)(mtile * 128 + r1c) * 8192 + q1 * 16;
    const char* pB  = (const char*)g_Bsign + (size_t)(ntile * 128 + r0c) * 8192 + q0 * 16;
    const char* pB2 = (const char*)g_Bsign + (size_t)(ntile * 128 + r1c) * 8192 + q1 * 16;

    const uint32_t d0off = (uint32_t)(r0c * ROW_BYTES + q0 * 16);
    const uint32_t d1off = (uint32_t)(r1c * ROW_BYTES + q1 * 16);

    auto load_stage = [&](int s, int kt) {
        const uint32_t st = smem_base + s * STAGE_BYTES;
        const size_t kb = (size_t)kt * 64;   // 32 bf16 = 64 bytes
        cp_async16(st + OFF_AHI + d0off, pAhi + kb);
        cp_async16(st + OFF_AHI + d1off, pAhi2 + kb);
        cp_async16(st + OFF_ALO + d0off, pAlo + kb);
        cp_async16(st + OFF_ALO + d1off, pAlo2 + kb);
        cp_async16(st + OFF_B + d0off, pB + kb);
        cp_async16(st + OFF_B + d1off, pB2 + kb);
        cp_commit();
    };

    // ---- fragment address bases (byte offsets within a stage) ----
    const uint32_t laneCol = (uint32_t)((lane & 3) * 4);
    const uint32_t laneRow = (uint32_t)(lane >> 2);
    uint32_t aRow[4], bRow[4];
    #pragma unroll
    for (int i = 0; i < 4; i++)
        aRow[i] = (uint32_t)((wm * 64 + i * 16 + laneRow) * ROW_BYTES) + laneCol;
    #pragma unroll
    for (int j = 0; j < 4; j++)
        bRow[j] = (uint32_t)(OFF_B + (wn * 32 + j * 8 + laneRow) * ROW_BYTES) + laneCol;

    float acc[4][4][4];
    #pragma unroll
    for (int i = 0; i < 4; i++)
        #pragma unroll
        for (int j = 0; j < 4; j++)
            #pragma unroll
            for (int r = 0; r < 4; r++) acc[i][j][r] = 0.0f;

    // ---- prologue: fill STAGES-1 stages ----
    #pragma unroll
    for (int s = 0; s < STAGES - 1; s++) load_stage(s, s);

    // ---- main loop ----
    for (int kt = 0; kt < NK; kt++) {
        cp_wait<STAGES - 2>();
        __syncthreads();

        if (kt + STAGES - 1 < NK) load_stage((kt + STAGES - 1) % STAGES, kt + STAGES - 1);

        const uint32_t st = smem_base + (kt % STAGES) * STAGE_BYTES;

        #pragma unroll
        for (int kk = 0; kk < 2; kk++) {
            const uint32_t ko = (uint32_t)(kk * 32);   // k16 byte offset within 64B row
            uint32_t bf[4][2];
            #pragma unroll
            for (int j = 0; j < 4; j++) {
                uint32_t ba = st + bRow[j] + ko;
                bf[j][0] = lds32(ba);
                bf[j][1] = lds32(ba + 16);
            }
            #pragma unroll
            for (int i = 0; i < 4; i++) {
                uint32_t aa = st + aRow[i] + ko;
                uint32_t ah0 = lds32(aa);
                uint32_t ah1 = lds32(aa + 8 * ROW_BYTES);
                uint32_t ah2 = lds32(aa + 16);
                uint32_t ah3 = lds32(aa + 8 * ROW_BYTES + 16);
                uint32_t la = aa + OFF_ALO;
                uint32_t al0 = lds32(la);
                uint32_t al1 = lds32(la + 8 * ROW_BYTES);
                uint32_t al2 = lds32(la + 16);
                uint32_t al3 = lds32(la + 8 * ROW_BYTES + 16);
                #pragma unroll
                for (int j = 0; j < 4; j++) {
                    mma16816(acc[i][j][0], acc[i][j][1], acc[i][j][2], acc[i][j][3],
                             ah0, ah1, ah2, ah3, bf[j][0], bf[j][1]);
                    mma16816(acc[i][j][0], acc[i][j][1], acc[i][j][2], acc[i][j][3],
                             al0, al1, al2, al3, bf[j][0], bf[j][1]);
                }
            }
        }
    }
    cp_wait<0>();

    // ---- epilogue: scale + store ----
    const float scl = g_scale;
    const int mbase = mtile * 128 + wm * 64 + (lane >> 2);
    const int nbase = ntile * 128 + wn * 32 + (lane & 3) * 2;
    #pragma unroll
    for (int i = 0; i < 4; i++) {
        const int r0 = mbase + i * 16;
        #pragma unroll
        for (int j = 0; j < 4; j++) {
            const int c = nbase + j * 8;
            float2 v0 = make_float2(acc[i][j][0] * scl, acc[i][j][1] * scl);
            float2 v1 = make_float2(acc[i][j][2] * scl, acc[i][j][3] * scl);
            *reinterpret_cast<float2*>(out + (size_t)r0 * N_TOTAL + c) = v0;
            *reinterpret_cast<float2*>(out + (size_t)(r0 + 8) * N_TOTAL + c) = v1;
        }
    }
}

// ---------------------------------------------------------------------------
// Host launch
// ---------------------------------------------------------------------------
extern "C" void kernel_launch(void* const* d_in, const int* in_sizes, int n_in,
                              void* d_out, int out_size) {
    const float* x = (const float*)d_in[0];
    const float* W = (const float*)d_in[1];
    float* out = (float*)d_out;

    // Not a stream operation; safe under graph capture; idempotent and
    // called unconditionally (no static guards per harness rules).
    cudaFuncSetAttribute(gemm_kernel, cudaFuncAttributeMaxDynamicSharedMemorySize,
                         SMEM_TOTAL);

    binarize_reduce_kernel<<<1024, 256>>>(W);
    finalize_scale_kernel<<<1, 256>>>();
    convert_x_kernel<<<32768, 256>>>(x);
    gemm_kernel<<<dim3(N_TOTAL / CTA_N, M_TOTAL / CTA_M, 1), 256, SMEM_TOTAL>>>(out);
}

// round 5
// speedup vs baseline: 2.2784x; 2.2784x over previous
#include <cuda.h>
#include <cuda_runtime.h>
#include <cuda_bf16.h>
#include <cuda_fp16.h>
#include <cstdint>

// ============================================================================
// y[8192,4096] = mean(|W|) * (x[8192,4096] @ sign(W)[4096,4096]^T)
// Round 4: single-pass fp16 GEMM (mma.sync m16n8k16 f16 -> f32 accum),
// ldmatrix fragment loads, 2 CTAs/SM (smem 80KB/CTA), scale in epilogue.
// ============================================================================

#define M_TOTAL 8192
#define N_TOTAL 4096
#define K_TOTAL 4096

#define CTA_M 128
#define CTA_N 128
#define K_STEP 32
#define NK (K_TOTAL / K_STEP)    // 128
#define STAGES 4

// SMEM per stage: A[128][32] fp16 rows padded to 80B, B[128][32] same
#define ROW_BYTES 80                       // 64 data + 16 pad (conflict-free)
#define TILE_BYTES (128 * ROW_BYTES)       // 10240
#define OFF_A 0
#define OFF_B TILE_BYTES
#define STAGE_BYTES (2 * TILE_BYTES)       // 20480
#define SMEM_TOTAL (STAGES * STAGE_BYTES)  // 81920

// ---------------------------------------------------------------------------
// Device scratch (allocation-free rule: __device__ globals)
// ---------------------------------------------------------------------------
__device__ __align__(1024) __half g_Ah[(size_t)M_TOTAL * K_TOTAL];
__device__ __align__(1024) __half g_Bsign[(size_t)N_TOTAL * K_TOTAL];
__device__ float g_partials[1024];
__device__ float g_scale;

// ---------------------------------------------------------------------------
// PTX helpers (sm_80-era, legal on base sm_103)
// ---------------------------------------------------------------------------
__device__ __forceinline__ uint32_t smem_to_u32(const void* p) {
    uint32_t a;
    asm("{ .reg .u64 t; cvta.to.shared.u64 t, %1; cvt.u32.u64 %0, t; }" : "=r"(a) : "l"(p));
    return a;
}

__device__ __forceinline__ void cp_async16(uint32_t dst, const void* src) {
    asm volatile("cp.async.cg.shared.global [%0], [%1], 16;" :: "r"(dst), "l"(src) : "memory");
}
__device__ __forceinline__ void cp_commit() {
    asm volatile("cp.async.commit_group;" ::: "memory");
}
template <int N>
__device__ __forceinline__ void cp_wait() {
    asm volatile("cp.async.wait_group %0;" :: "n"(N) : "memory");
}

__device__ __forceinline__ void ldmatrix_x4(uint32_t& r0, uint32_t& r1,
                                            uint32_t& r2, uint32_t& r3, uint32_t addr) {
    asm volatile("ldmatrix.sync.aligned.m8n8.x4.shared.b16 {%0,%1,%2,%3}, [%4];"
                 : "=r"(r0), "=r"(r1), "=r"(r2), "=r"(r3) : "r"(addr));
}

__device__ __forceinline__ void mma16816(float& d0, float& d1, float& d2, float& d3,
                                         uint32_t a0, uint32_t a1, uint32_t a2, uint32_t a3,
                                         uint32_t b0, uint32_t b1) {
    asm volatile(
        "mma.sync.aligned.m16n8k16.row.col.f32.f16.f16.f32 "
        "{%0,%1,%2,%3}, {%4,%5,%6,%7}, {%8,%9}, {%0,%1,%2,%3};"
        : "+f"(d0), "+f"(d1), "+f"(d2), "+f"(d3)
        : "r"(a0), "r"(a1), "r"(a2), "r"(a3), "r"(b0), "r"(b1));
}

// ---------------------------------------------------------------------------
// Prep kernel 1: binarize W -> fp16 sign AND partial |W| sums (deterministic)
// ---------------------------------------------------------------------------
__global__ void binarize_reduce_kernel(const float* __restrict__ W) {
    __shared__ float sdata[256];
    size_t base = (size_t)blockIdx.x * 16384;
    float s = 0.0f;
    for (int i = threadIdx.x; i < 16384; i += 256) {
        float w = W[base + i];
        s += fabsf(w);
        float sg = (w > 0.0f) ? 1.0f : ((w < 0.0f) ? -1.0f : 0.0f);
        g_Bsign[base + i] = __float2half(sg);
    }
    sdata[threadIdx.x] = s;
    __syncthreads();
    for (int off = 128; off > 0; off >>= 1) {
        if (threadIdx.x < off) sdata[threadIdx.x] += sdata[threadIdx.x + off];
        __syncthreads();
    }
    if (threadIdx.x == 0) g_partials[blockIdx.x] = sdata[0];
}

__global__ void finalize_scale_kernel() {
    __shared__ float sdata[256];
    int t = threadIdx.x;
    float s = 0.0f;
    #pragma unroll
    for (int i = 0; i < 4; i++) s += g_partials[t * 4 + i];
    sdata[t] = s;
    __syncthreads();
    for (int off = 128; off > 0; off >>= 1) {
        if (t < off) sdata[t] += sdata[t + off];
        __syncthreads();
    }
    if (t == 0) g_scale = sdata[0] * (1.0f / 16777216.0f);
}

// Prep kernel 3: x (fp32) -> fp16. 8388608 float4 vectors.
__global__ void convert_x_kernel(const float* __restrict__ x) {
    size_t i = (size_t)blockIdx.x * 256 + threadIdx.x;
    float4 v = reinterpret_cast<const float4*>(x)[i];
    __half h0 = __float2half_rn(v.x);
    __half h1 = __float2half_rn(v.y);
    __half h2 = __float2half_rn(v.z);
    __half h3 = __float2half_rn(v.w);
    ushort4 hv = make_ushort4(__half_as_ushort(h0), __half_as_ushort(h1),
                              __half_as_ushort(h2), __half_as_ushort(h3));
    reinterpret_cast<ushort4*>(g_Ah)[i] = hv;
}

// ---------------------------------------------------------------------------
// GEMM kernel: multistage cp.async + ldmatrix + mma.sync (fp16, f32 accum)
// 256 threads = 8 warps, warp grid 2(M) x 4(N), warp tile 64x32, 2 CTAs/SM
// ---------------------------------------------------------------------------
__global__ void __launch_bounds__(256, 2) gemm_kernel(float* __restrict__ out) {
    extern __shared__ __align__(128) char smem[];
    const uint32_t smem_base = smem_to_u32(smem);

    const int tid = threadIdx.x;
    const int lane = tid & 31;
    const int wid = tid >> 5;
    const int wm = wid & 1;       // 0..1
    const int wn = wid >> 1;      // 0..3
    const int ntile = blockIdx.x; // 0..31
    const int mtile = blockIdx.y; // 0..63

    // ---- cp.async source pointers ----
    // Per stage: A 512 chunks (16B) + B 512 chunks; thread handles chunks
    // tid and tid+256 in each tile. chunk c -> row c>>2, quad c&3.
    const int c0 = tid, c1 = tid + 256;
    const int r0c = c0 >> 2, q0 = c0 & 3;
    const int r1c = c1 >> 2, q1 = c1 & 3;

    const char* pA  = (const char*)g_Ah + (size_t)(mtile * 128 + r0c) * 8192 + q0 * 16;
    const char* pA2 = (const char*)g_Ah + (size_t)(mtile * 128 + r1c) * 8192 + q1 * 16;
    const char* pB  = (const char*)g_Bsign + (size_t)(ntile * 128 + r0c) * 8192 + q0 * 16;
    const char* pB2 = (const char*)g_Bsign + (size_t)(ntile * 128 + r1c) * 8192 + q1 * 16;

    const uint32_t d0off = (uint32_t)(r0c * ROW_BYTES + q0 * 16);
    const uint32_t d1off = (uint32_t)(r1c * ROW_BYTES + q1 * 16);

    auto load_stage = [&](int s, int kt) {
        const uint32_t st = smem_base + s * STAGE_BYTES;
        const size_t kb = (size_t)kt * 64;   // 32 fp16 = 64 bytes
        cp_async16(st + OFF_A + d0off, pA + kb);
        cp_async16(st + OFF_A + d1off, pA2 + kb);
        cp_async16(st + OFF_B + d0off, pB + kb);
        cp_async16(st + OFF_B + d1off, pB2 + kb);
        cp_commit();
    };

    // ---- ldmatrix per-lane addresses (byte offsets within a stage) ----
    // A x4 tile (16x16): m0=rows0-7 k0-7, m1=rows8-15 k0-7, m2=rows0-7 k8-15, m3=rows8-15 k8-15
    const uint32_t aLaneRow = (uint32_t)(lane & 15);
    const uint32_t aLaneCol = (uint32_t)((lane >> 4) * 16);
    const uint32_t aBase = OFF_A + (wm * 64 + aLaneRow) * ROW_BYTES + aLaneCol;
    // B x4 over an n16 x k16 block: m0=n0-7 k0-7, m1=n0-7 k8-15, m2=n8-15 k0-7, m3=n8-15 k8-15
    const uint32_t bLaneRow = (uint32_t)((lane & 7) + ((lane >> 4) & 1) * 8);
    const uint32_t bLaneCol = (uint32_t)(((lane >> 3) & 1) * 16);
    const uint32_t bBase = OFF_B + (wn * 32 + bLaneRow) * ROW_BYTES + bLaneCol;

    float acc[4][4][4];
    #pragma unroll
    for (int i = 0; i < 4; i++)
        #pragma unroll
        for (int j = 0; j < 4; j++)
            #pragma unroll
            for (int r = 0; r < 4; r++) acc[i][j][r] = 0.0f;

    // ---- prologue ----
    #pragma unroll
    for (int s = 0; s < STAGES - 1; s++) load_stage(s, s);

    // ---- main loop ----
    for (int kt = 0; kt < NK; kt++) {
        cp_wait<STAGES - 2>();
        __syncthreads();

        if (kt + STAGES - 1 < NK) load_stage((kt + STAGES - 1) % STAGES, kt + STAGES - 1);

        const uint32_t st = smem_base + (kt % STAGES) * STAGE_BYTES;

        #pragma unroll
        for (int kk = 0; kk < 2; kk++) {
            const uint32_t ko = (uint32_t)(kk * 32);   // k16 = 32 bytes
            // B fragments: 2 x ldmatrix.x4 covering j=0..3
            uint32_t bq[8];
            ldmatrix_x4(bq[0], bq[1], bq[2], bq[3], st + bBase + ko);                  // n0-15
            ldmatrix_x4(bq[4], bq[5], bq[6], bq[7], st + bBase + 16 * ROW_BYTES + ko); // n16-31
            #pragma unroll
            for (int i = 0; i < 4; i++) {
                uint32_t a0, a1, a2, a3;
                ldmatrix_x4(a0, a1, a2, a3, st + aBase + (uint32_t)(i * 16 * ROW_BYTES) + ko);
                #pragma unroll
                for (int j = 0; j < 4; j++) {
                    mma16816(acc[i][j][0], acc[i][j][1], acc[i][j][2], acc[i][j][3],
                             a0, a1, a2, a3, bq[2 * j], bq[2 * j + 1]);
                }
            }
        }
    }
    cp_wait<0>();

    // ---- epilogue: scale + store ----
    const float scl = g_scale;
    const int mbase = mtile * 128 + wm * 64 + (lane >> 2);
    const int nbase = ntile * 128 + wn * 32 + (lane & 3) * 2;
    #pragma unroll
    for (int i = 0; i < 4; i++) {
        const int r0 = mbase + i * 16;
        #pragma unroll
        for (int j = 0; j < 4; j++) {
            const int c = nbase + j * 8;
            float2 v0 = make_float2(acc[i][j][0] * scl, acc[i][j][1] * scl);
            float2 v1 = make_float2(acc[i][j][2] * scl, acc[i][j][3] * scl);
            *reinterpret_cast<float2*>(out + (size_t)r0 * N_TOTAL + c) = v0;
            *reinterpret_cast<float2*>(out + (size_t)(r0 + 8) * N_TOTAL + c) = v1;
        }
    }
}

// ---------------------------------------------------------------------------
// Host launch
// ---------------------------------------------------------------------------
extern "C" void kernel_launch(void* const* d_in, const int* in_sizes, int n_in,
                              void* d_out, int out_size) {
    const float* x = (const float*)d_in[0];
    const float* W = (const float*)d_in[1];
    float* out = (float*)d_out;

    cudaFuncSetAttribute(gemm_kernel, cudaFuncAttributeMaxDynamicSharedMemorySize,
                         SMEM_TOTAL);

    binarize_reduce_kernel<<<1024, 256>>>(W);
    finalize_scale_kernel<<<1, 256>>>();
    convert_x_kernel<<<32768, 256>>>(x);
    gemm_kernel<<<dim3(N_TOTAL / CTA_N, M_TOTAL / CTA_M, 1), 256, SMEM_TOTAL>>>(out);
}